// round 2
// baseline (speedup 1.0000x reference)
#include <cuda_runtime.h>
#include <math.h>
#include <stdint.h>

// ---------------- problem constants ----------------
#define BB 8
#define NN 16384
#define SS 4096
#define KK 32
#define CC 64
#define NCOL (BB*SS*KK)          // 1048576 columns (b,s,k)
#define BN_EPS 1e-5f
#define INF_F 3.0e38f

// ---------------- scratch layout (floats) ----------------
#define OFF_FEATS_T ((size_t)0)
#define OFF_XYZT    ((size_t)8388608)
#define OFF_NXYZT   ((size_t)8912896)
#define OFF_A       ((size_t)9043968)
#define OFF_B       ((size_t)79298560)
#define OFF_C       ((size_t)146407424)
#define SCR_TOTAL   ((size_t)280625152)   // ~1.05 GB

__device__ float g_scr[SCR_TOTAL];
__device__ int   g_idx[SS*KK];
__device__ float g_sum[3*128];
__device__ float g_sq [3*128];
__device__ float g_bna[3*128];
__device__ float g_bnc[3*128];

static __device__ __forceinline__ int clampN(int n) {
    return n < 0 ? 0 : (n >= NN ? NN-1 : n);
}

// ---------------- prep: new_xyz output + query coords + clear stats ----------------
__global__ void __launch_bounds__(256) k_newxyz(const float* __restrict__ xyz,
                                                const int* __restrict__ perm,
                                                float* __restrict__ out) {
    int t = blockIdx.x*256 + threadIdx.x;
    if (t < 3*128) { g_sum[t] = 0.f; g_sq[t] = 0.f; }
    if (t >= BB*SS) return;
    int b = t / SS, s = t % SS;
    int n = clampN(perm[s]);
    #pragma unroll
    for (int c = 0; c < 3; ++c) {
        float v = xyz[((size_t)b*3 + c)*NN + n];
        out[((size_t)b*3 + c)*SS + s] = v;
        g_scr[OFF_NXYZT + ((size_t)(b*SS + s))*4 + c] = v;
    }
    g_scr[OFF_NXYZT + ((size_t)(b*SS + s))*4 + 3] = 0.f;
}

// ---------------- prep: xyz transpose (B,3,N) -> (B,N,4) ----------------
__global__ void __launch_bounds__(256) k_xyzt(const float* __restrict__ xyz) {
    int t = blockIdx.x*256 + threadIdx.x;
    if (t >= BB*NN) return;
    int b = t >> 14, n = t & (NN-1);
    #pragma unroll
    for (int c = 0; c < 3; ++c)
        g_scr[OFF_XYZT + ((size_t)(b*NN + n))*4 + c] = xyz[((size_t)b*3 + c)*NN + n];
    g_scr[OFF_XYZT + ((size_t)(b*NN + n))*4 + 3] = 0.f;
}

// ---------------- prep: feats transpose (B,64,N) -> (B,N,64) ----------------
__global__ void __launch_bounds__(256) k_featst(const float* __restrict__ feats) {
    __shared__ float tile[32][33];
    int blk = blockIdx.x;
    int nb  = blk & 511;           // N/32 = 512
    int tmp = blk >> 9;
    int cb  = tmp & 1;             // C/32 = 2
    int b   = tmp >> 1;
    int tx = threadIdx.x & 31, ty = threadIdx.x >> 5;   // ty 0..7
    int n0 = nb*32, c0 = cb*32;
    #pragma unroll
    for (int i = 0; i < 32; i += 8)
        tile[ty+i][tx] = feats[((size_t)b*CC + c0 + ty + i)*NN + n0 + tx];
    __syncthreads();
    #pragma unroll
    for (int i = 0; i < 32; i += 8)
        g_scr[OFF_FEATS_T + ((size_t)b*NN + n0 + ty + i)*CC + c0 + tx] = tile[tx][ty+i];
}

// ---------------- KNN: 8 threads per query, tiled support, local top-32 ----------------
__global__ void __launch_bounds__(128) k_knn() {
    __shared__ float4 s_tile[2048];          // 32KB; reused as merge buffer
    int tid = threadIdx.x;
    int ql = tid >> 3, sl = tid & 7;
    int q = blockIdx.x*16 + ql;
    const float4* xt = (const float4*)(g_scr + OFF_XYZT);      // batch 0 rows first
    float4 qp = ((const float4*)(g_scr + OFF_NXYZT))[q];       // batch 0 query
    float qq = qp.x*qp.x + qp.y*qp.y + qp.z*qp.z;

    float bd[32]; int bi[32];
    #pragma unroll
    for (int r = 0; r < 32; ++r) { bd[r] = INF_F; bi[r] = 0; }
    float worst = INF_F; int wpos = 0;

    for (int tile = 0; tile < 8; ++tile) {
        __syncthreads();
        for (int i = tid; i < 2048; i += 128) {
            float4 p = xt[tile*2048 + i];
            p.w = p.x*p.x + p.y*p.y + p.z*p.z;
            s_tile[i] = p;
        }
        __syncthreads();
        for (int j = sl; j < 2048; j += 8) {
            float4 p = s_tile[j];
            float d = qq - 2.f*(qp.x*p.x + qp.y*p.y + qp.z*p.z) + p.w;
            if (d < worst) {
                bd[wpos] = d; bi[wpos] = tile*2048 + j;
                worst = bd[0]; wpos = 0;
                #pragma unroll
                for (int r = 1; r < 32; ++r)
                    if (bd[r] > worst) { worst = bd[r]; wpos = r; }
            }
        }
    }
    __syncthreads();
    float* md = (float*)s_tile;              // 4096 floats
    int*   mi = ((int*)s_tile) + 4096;       // 4096 ints
    #pragma unroll
    for (int r = 0; r < 32; ++r) {
        md[(ql*8 + sl)*32 + r] = bd[r];
        mi[(ql*8 + sl)*32 + r] = bi[r];
    }
    __syncthreads();
    if (sl == 0) {
        #pragma unroll
        for (int r = 0; r < 32; ++r) bd[r] = INF_F;
        worst = INF_F; wpos = 0;
        for (int j = 0; j < 256; ++j) {
            float d = md[ql*256 + j];
            if (d < worst) {
                bd[wpos] = d; bi[wpos] = mi[ql*256 + j];
                worst = bd[0]; wpos = 0;
                #pragma unroll
                for (int r = 1; r < 32; ++r)
                    if (bd[r] > worst) { worst = bd[r]; wpos = r; }
            }
        }
        #pragma unroll
        for (int r = 0; r < 32; ++r) g_idx[q*32 + r] = bi[r];
    }
}

// ---------------- build X0 (67 x NCOL), channel-major ----------------
__global__ void __launch_bounds__(128) k_buildx0() {
    __shared__ float sh[67][128];
    int tid = threadIdx.x;
    int col = blockIdx.x*128 + tid;
    int G = col >> 5, k = col & 31;
    int s = G & (SS-1), b = G >> 12;
    int n = clampN(g_idx[s*32 + k]);
    const float4* fr = (const float4*)(g_scr + OFF_FEATS_T + ((size_t)b*NN + n)*CC);
    #pragma unroll
    for (int i = 0; i < 16; ++i) {
        float4 v = fr[i];
        sh[i*4+0][tid] = v.x; sh[i*4+1][tid] = v.y;
        sh[i*4+2][tid] = v.z; sh[i*4+3][tid] = v.w;
    }
    float4 p  = ((const float4*)(g_scr + OFF_XYZT))[(size_t)b*NN + n];
    float4 qc = ((const float4*)(g_scr + OFF_NXYZT))[(size_t)b*SS + s];
    sh[64][tid] = p.x - qc.x;
    sh[65][tid] = p.y - qc.y;
    sh[66][tid] = p.z - qc.z;
    __syncthreads();
    size_t base = (size_t)blockIdx.x*128;
    for (int c = 0; c < 67; ++c)
        g_scr[OFF_A + (size_t)c*NCOL + base + tid] = sh[c][tid];
}

// ---------------- fused GEMM (+input BN/ReLU) + per-row stats ----------------
#define FMA4(A, W) { A.x = fmaf((W), xv.x, A.x); A.y = fmaf((W), xv.y, A.y); \
                     A.z = fmaf((W), xv.z, A.z); A.w = fmaf((W), xv.w, A.w); }

template<int M, int KIN, bool BN>
__global__ void __launch_bounds__(M*4) k_gemm(size_t xoff, size_t zoff,
                                              const float* __restrict__ W,
                                              int bnSlot, int statSlot) {
    extern __shared__ float smem[];
    float* shx = smem;               // KIN * 128
    float* shw = smem + KIN*128;     // KIN * M (transposed)
    const int THREADS = M*4;
    int tid = threadIdx.x;
    int tx = tid & 31, ty = tid >> 5;

    for (int i = tid; i < M*KIN; i += THREADS) {
        int m = i / KIN, kk = i - m*KIN;
        shw[kk*M + m] = W[i];
    }
    size_t cb = (size_t)blockIdx.x * 128;
    const float* bnA = g_bna + bnSlot*128;
    const float* bnC = g_bnc + bnSlot*128;
    for (int i = tid; i < KIN*128; i += THREADS) {
        int kk = i >> 7, cc = i & 127;
        float v = g_scr[xoff + (size_t)kk*NCOL + cb + cc];
        if (BN) v = fmaxf(fmaf(bnA[kk], v, bnC[kk]), 0.f);
        shx[kk*128 + cc] = v;
    }
    __syncthreads();

    float4 a0 = {0,0,0,0}, a1 = a0, a2 = a0, a3 = a0, a4 = a0, a5 = a0, a6 = a0, a7 = a0;
    #pragma unroll 4
    for (int kk = 0; kk < KIN; ++kk) {
        float4 xv = *(const float4*)(shx + kk*128 + tx*4);
        const float* wr = shw + kk*M + ty*8;
        float4 wa = *(const float4*)(wr);
        float4 wb = *(const float4*)(wr + 4);
        FMA4(a0, wa.x) FMA4(a1, wa.y) FMA4(a2, wa.z) FMA4(a3, wa.w)
        FMA4(a4, wb.x) FMA4(a5, wb.y) FMA4(a6, wb.z) FMA4(a7, wb.w)
    }

    float* sump = g_sum + statSlot*128;
    float* sqp  = g_sq  + statSlot*128;
    float* zb   = g_scr + zoff + cb + tx*4;
    #define ROWOUT(A, I) { \
        *(float4*)(zb + (size_t)(ty*8 + (I))*NCOL) = A; \
        float s_ = A.x + A.y + A.z + A.w; \
        float q_ = A.x*A.x + A.y*A.y + A.z*A.z + A.w*A.w; \
        for (int o_ = 16; o_ > 0; o_ >>= 1) { \
            s_ += __shfl_down_sync(0xffffffffu, s_, o_); \
            q_ += __shfl_down_sync(0xffffffffu, q_, o_); } \
        if (tx == 0) { atomicAdd(sump + ty*8 + (I), s_); atomicAdd(sqp + ty*8 + (I), q_); } }
    ROWOUT(a0,0) ROWOUT(a1,1) ROWOUT(a2,2) ROWOUT(a3,3)
    ROWOUT(a4,4) ROWOUT(a5,5) ROWOUT(a6,6) ROWOUT(a7,7)
    #undef ROWOUT
}

// ---------------- BN affine params from stats ----------------
__global__ void k_bnparam(int slot, const float* __restrict__ g,
                          const float* __restrict__ b, int M) {
    int m = threadIdx.x;
    if (m >= M) return;
    const float cnt = (float)NCOL;
    float mu  = g_sum[slot*128 + m] / cnt;
    float var = g_sq [slot*128 + m] / cnt - mu*mu;
    float a = g[m] * rsqrtf(var + BN_EPS);
    g_bna[slot*128 + m] = a;
    g_bnc[slot*128 + m] = b[m] - mu*a;
}

// ---------------- finalize: BN3 + ReLU + max over K ----------------
__global__ void __launch_bounds__(256) k_final(float* __restrict__ out) {
    int t = blockIdx.x*256 + threadIdx.x;
    if (t >= BB*128*SS) return;
    int s  = t & (SS-1);
    int bc = t >> 12;
    int c = bc & 127, b = bc >> 7;
    float a  = g_bna[2*128 + c];
    float cc = g_bnc[2*128 + c];
    const float4* z = (const float4*)(g_scr + OFF_C + (size_t)c*NCOL + (((size_t)(b*SS + s)) << 5));
    float m = 0.f;   // ReLU floor: max_k relu(x) == max(max_k x, 0)
    #pragma unroll
    for (int i = 0; i < 8; ++i) {
        float4 v = z[i];
        m = fmaxf(m, fmaf(a, v.x, cc));
        m = fmaxf(m, fmaf(a, v.y, cc));
        m = fmaxf(m, fmaf(a, v.z, cc));
        m = fmaxf(m, fmaf(a, v.w, cc));
    }
    out[BB*3*SS + t] = m;
}

// ---------------- launch ----------------
extern "C" void kernel_launch(void* const* d_in, const int* in_sizes, int n_in,
                              void* d_out, int out_size) {
    (void)in_sizes; (void)n_in; (void)out_size;
    const float* xyz   = (const float*)d_in[0];
    const float* feats = (const float*)d_in[1];
    const int*   perm  = (const int*)d_in[2];     // JAX w/o x64: int64 cast -> int32
    const float* w0 = (const float*)d_in[3];
    const float* g0 = (const float*)d_in[4];
    const float* b0 = (const float*)d_in[5];
    const float* w1 = (const float*)d_in[6];
    const float* g1 = (const float*)d_in[7];
    const float* b1 = (const float*)d_in[8];
    const float* w2 = (const float*)d_in[9];
    const float* g2 = (const float*)d_in[10];
    const float* b2 = (const float*)d_in[11];
    float* out = (float*)d_out;

    const int sm1 = (67*128 + 67*64)  * 4;   // 51456
    const int sm2 = (64*128 + 64*64)  * 4;   // 49152
    const int sm3 = (64*128 + 64*128) * 4;   // 65536
    cudaFuncSetAttribute(k_gemm<64,67,false>, cudaFuncAttributeMaxDynamicSharedMemorySize, sm1);
    cudaFuncSetAttribute(k_gemm<64,64,true >, cudaFuncAttributeMaxDynamicSharedMemorySize, sm2);
    cudaFuncSetAttribute(k_gemm<128,64,true>, cudaFuncAttributeMaxDynamicSharedMemorySize, sm3);

    k_newxyz<<<(BB*SS)/256, 256>>>(xyz, perm, out);
    k_xyzt  <<<(BB*NN)/256, 256>>>(xyz);
    k_featst<<<BB*2*(NN/32), 256>>>(feats);
    k_knn   <<<SS/16, 128>>>();
    k_buildx0<<<NCOL/128, 128>>>();

    k_gemm<64,67,false><<<NCOL/128, 256, sm1>>>(OFF_A, OFF_B, w0, 0, 0);
    k_bnparam<<<1,128>>>(0, g0, b0, 64);
    k_gemm<64,64,true ><<<NCOL/128, 256, sm2>>>(OFF_B, OFF_A, w1, 0, 1);
    k_bnparam<<<1,128>>>(1, g1, b1, 64);
    k_gemm<128,64,true><<<NCOL/128, 512, sm3>>>(OFF_A, OFF_C, w2, 1, 2);
    k_bnparam<<<1,128>>>(2, g2, b2, 128);
    k_final<<<(BB*128*SS)/256, 256>>>(out);
}

// round 3
// speedup vs baseline: 1.4440x; 1.4440x over previous
#include <cuda_runtime.h>
#include <math.h>
#include <stdint.h>

// ---------------- problem constants ----------------
#define BB 8
#define NN 16384
#define SS 4096
#define KK 32
#define CC 64
#define NCOL (BB*SS*KK)          // 1048576 columns (b,s,k)
#define BN_EPS 1e-5f
#define INF_F 3.0e38f

// ---------------- scratch layout (floats) ----------------
#define OFF_FEATS_T ((size_t)0)
#define OFF_XYZT    ((size_t)8388608)
#define OFF_NXYZT   ((size_t)8912896)
#define OFF_A       ((size_t)9043968)
#define OFF_B       ((size_t)79298560)
#define OFF_C       ((size_t)146407424)
#define SCR_TOTAL   ((size_t)280625152)   // ~1.05 GB

__device__ float g_scr[SCR_TOTAL];
__device__ int   g_idx[SS*KK];
__device__ float g_sum[3*128];
__device__ float g_sq [3*128];
__device__ float g_bna[3*128];
__device__ float g_bnc[3*128];

static __device__ __forceinline__ int clampN(int n) {
    return n < 0 ? 0 : (n >= NN ? NN-1 : n);
}

// ---------------- prep: new_xyz output + query coords + clear stats ----------------
__global__ void __launch_bounds__(256) k_newxyz(const float* __restrict__ xyz,
                                                const int* __restrict__ perm,
                                                float* __restrict__ out) {
    int t = blockIdx.x*256 + threadIdx.x;
    if (t < 3*128) { g_sum[t] = 0.f; g_sq[t] = 0.f; }
    if (t >= BB*SS) return;
    int b = t / SS, s = t % SS;
    int n = clampN(perm[s]);
    #pragma unroll
    for (int c = 0; c < 3; ++c) {
        float v = xyz[((size_t)b*3 + c)*NN + n];
        out[((size_t)b*3 + c)*SS + s] = v;
        g_scr[OFF_NXYZT + ((size_t)(b*SS + s))*4 + c] = v;
    }
    g_scr[OFF_NXYZT + ((size_t)(b*SS + s))*4 + 3] = 0.f;
}

// ---------------- prep: xyz transpose (B,3,N) -> (B,N,4) ----------------
__global__ void __launch_bounds__(256) k_xyzt(const float* __restrict__ xyz) {
    int t = blockIdx.x*256 + threadIdx.x;
    if (t >= BB*NN) return;
    int b = t >> 14, n = t & (NN-1);
    #pragma unroll
    for (int c = 0; c < 3; ++c)
        g_scr[OFF_XYZT + ((size_t)(b*NN + n))*4 + c] = xyz[((size_t)b*3 + c)*NN + n];
    g_scr[OFF_XYZT + ((size_t)(b*NN + n))*4 + 3] = 0.f;
}

// ---------------- prep: feats transpose (B,64,N) -> (B,N,64) ----------------
__global__ void __launch_bounds__(256) k_featst(const float* __restrict__ feats) {
    __shared__ float tile[32][33];
    int blk = blockIdx.x;
    int nb  = blk & 511;           // N/32 = 512
    int tmp = blk >> 9;
    int cb  = tmp & 1;             // C/32 = 2
    int b   = tmp >> 1;
    int tx = threadIdx.x & 31, ty = threadIdx.x >> 5;   // ty 0..7
    int n0 = nb*32, c0 = cb*32;
    #pragma unroll
    for (int i = 0; i < 32; i += 8)
        tile[ty+i][tx] = feats[((size_t)b*CC + c0 + ty + i)*NN + n0 + tx];
    __syncthreads();
    #pragma unroll
    for (int i = 0; i < 32; i += 8)
        g_scr[OFF_FEATS_T + ((size_t)b*NN + n0 + ty + i)*CC + c0 + tx] = tile[tx][ty+i];
}

// ---------------- KNN: one warp per query, distributed register top-32 ----------------
// Lane L of the warp owns list entry L as a (float,int) register pair. A candidate
// beating `worst` (warp-uniform max of the 32 entries) triggers: butterfly argmax
// to find the worst slot, owner-lane replaces its entry, butterfly max to refresh
// `worst`. Expected insertions per warp ~ 32*ln(16384/32) ~ 200.
__global__ void __launch_bounds__(256) k_knn() {
    __shared__ float4 s_tile[2048];          // 32KB support tile (shared by 8 warps)
    int tid = threadIdx.x;
    int w = tid >> 5, lane = tid & 31;
    int q = blockIdx.x*8 + w;
    const float4* xt = (const float4*)(g_scr + OFF_XYZT);      // batch 0
    float4 qp = ((const float4*)(g_scr + OFF_NXYZT))[q];       // batch 0 query
    float qq = qp.x*qp.x + qp.y*qp.y + qp.z*qp.z;

    float myd = INF_F;           // this lane's list entry
    int   myi = 0;
    float worst = INF_F;         // warp-uniform max of all 32 entries

    for (int tile = 0; tile < 8; ++tile) {
        __syncthreads();
        for (int i = tid; i < 2048; i += 256) {
            float4 p = xt[tile*2048 + i];
            p.w = p.x*p.x + p.y*p.y + p.z*p.z;
            s_tile[i] = p;
        }
        __syncthreads();
        #pragma unroll 4
        for (int j = 0; j < 64; ++j) {
            int ii = j*32 + lane;
            float4 p = s_tile[ii];
            float d = qq - 2.f*(qp.x*p.x + qp.y*p.y + qp.z*p.z) + p.w;
            int idx = tile*2048 + ii;
            unsigned hits = __ballot_sync(0xffffffffu, d < worst);
            while (hits) {
                int src = __ffs(hits) - 1;
                hits &= hits - 1;
                float dc = __shfl_sync(0xffffffffu, d, src);
                int   ic = __shfl_sync(0xffffffffu, idx, src);
                if (dc < worst) {
                    // argmax over the 32 distributed entries
                    float v = myd; int pos = lane;
                    #pragma unroll
                    for (int off = 16; off; off >>= 1) {
                        float ov = __shfl_xor_sync(0xffffffffu, v, off);
                        int   op = __shfl_xor_sync(0xffffffffu, pos, off);
                        if (ov > v || (ov == v && op < pos)) { v = ov; pos = op; }
                    }
                    if (lane == pos) { myd = dc; myi = ic; }
                    // refresh warp-uniform worst
                    float m = myd;
                    #pragma unroll
                    for (int off = 16; off; off >>= 1)
                        m = fmaxf(m, __shfl_xor_sync(0xffffffffu, m, off));
                    worst = m;
                }
            }
        }
    }
    g_idx[q*32 + lane] = myi;
}

// ---------------- build X0 (67 x NCOL), channel-major ----------------
__global__ void __launch_bounds__(128) k_buildx0() {
    __shared__ float sh[67][128];
    int tid = threadIdx.x;
    int col = blockIdx.x*128 + tid;
    int G = col >> 5, k = col & 31;
    int s = G & (SS-1), b = G >> 12;
    int n = clampN(g_idx[s*32 + k]);
    const float4* fr = (const float4*)(g_scr + OFF_FEATS_T + ((size_t)b*NN + n)*CC);
    #pragma unroll
    for (int i = 0; i < 16; ++i) {
        float4 v = fr[i];
        sh[i*4+0][tid] = v.x; sh[i*4+1][tid] = v.y;
        sh[i*4+2][tid] = v.z; sh[i*4+3][tid] = v.w;
    }
    float4 p  = ((const float4*)(g_scr + OFF_XYZT))[(size_t)b*NN + n];
    float4 qc = ((const float4*)(g_scr + OFF_NXYZT))[(size_t)b*SS + s];
    sh[64][tid] = p.x - qc.x;
    sh[65][tid] = p.y - qc.y;
    sh[66][tid] = p.z - qc.z;
    __syncthreads();
    size_t base = (size_t)blockIdx.x*128;
    for (int c = 0; c < 67; ++c)
        g_scr[OFF_A + (size_t)c*NCOL + base + tid] = sh[c][tid];
}

// ---------------- fused GEMM (+input BN/ReLU) + per-row stats, 8x8 thread tile ----------------
#define ROWFMA(AA, AB, WV) { \
    AA.x = fmaf((WV), x0.x, AA.x); AA.y = fmaf((WV), x0.y, AA.y); \
    AA.z = fmaf((WV), x0.z, AA.z); AA.w = fmaf((WV), x0.w, AA.w); \
    AB.x = fmaf((WV), x1.x, AB.x); AB.y = fmaf((WV), x1.y, AB.y); \
    AB.z = fmaf((WV), x1.z, AB.z); AB.w = fmaf((WV), x1.w, AB.w); }

template<int M, int KIN, bool BN>
__global__ void __launch_bounds__(M*2) k_gemm(size_t xoff, size_t zoff,
                                              const float* __restrict__ W,
                                              int bnSlot, int statSlot) {
    extern __shared__ float smem[];
    float* shx = smem;               // KIN * 128
    float* shw = smem + KIN*128;     // KIN * M (transposed)
    const int THREADS = M*2;
    int tid = threadIdx.x;
    int tx = tid & 15, ty = tid >> 4;       // 16 col-groups x (M/8) row-groups

    for (int i = tid; i < M*KIN; i += THREADS) {
        int m = i / KIN, kk = i - m*KIN;
        shw[kk*M + m] = W[i];
    }
    size_t cb = (size_t)blockIdx.x * 128;
    const float* bnA = g_bna + bnSlot*128;
    const float* bnC = g_bnc + bnSlot*128;
    for (int i = tid; i < KIN*128; i += THREADS) {
        int kk = i >> 7, cc = i & 127;
        float v = g_scr[xoff + (size_t)kk*NCOL + cb + cc];
        if (BN) v = fmaxf(fmaf(bnA[kk], v, bnC[kk]), 0.f);
        shx[kk*128 + cc] = v;
    }
    __syncthreads();

    float4 aA[8], aB[8];
    #pragma unroll
    for (int r = 0; r < 8; ++r) { aA[r] = make_float4(0,0,0,0); aB[r] = aA[r]; }

    #pragma unroll 4
    for (int kk = 0; kk < KIN; ++kk) {
        float4 x0 = *(const float4*)(shx + kk*128 + tx*8);
        float4 x1 = *(const float4*)(shx + kk*128 + tx*8 + 4);
        float4 w0 = *(const float4*)(shw + kk*M + ty*8);
        float4 w1 = *(const float4*)(shw + kk*M + ty*8 + 4);
        ROWFMA(aA[0], aB[0], w0.x) ROWFMA(aA[1], aB[1], w0.y)
        ROWFMA(aA[2], aB[2], w0.z) ROWFMA(aA[3], aB[3], w0.w)
        ROWFMA(aA[4], aB[4], w1.x) ROWFMA(aA[5], aB[5], w1.y)
        ROWFMA(aA[6], aB[6], w1.z) ROWFMA(aA[7], aB[7], w1.w)
    }

    float* sump = g_sum + statSlot*128;
    float* sqp  = g_sq  + statSlot*128;
    float* zb   = g_scr + zoff + cb + tx*8;
    #pragma unroll
    for (int r = 0; r < 8; ++r) {
        int m = ty*8 + r;
        float4 va = aA[r], vb = aB[r];
        *(float4*)(zb + (size_t)m*NCOL)     = va;
        *(float4*)(zb + (size_t)m*NCOL + 4) = vb;
        float s_ = va.x+va.y+va.z+va.w + vb.x+vb.y+vb.z+vb.w;
        float q_ = va.x*va.x+va.y*va.y+va.z*va.z+va.w*va.w
                 + vb.x*vb.x+vb.y*vb.y+vb.z*vb.z+vb.w*vb.w;
        #pragma unroll
        for (int o = 8; o; o >>= 1) {
            s_ += __shfl_down_sync(0xffffffffu, s_, o, 16);
            q_ += __shfl_down_sync(0xffffffffu, q_, o, 16);
        }
        if (tx == 0) { atomicAdd(sump + m, s_); atomicAdd(sqp + m, q_); }
    }
}

// ---------------- BN affine params from stats ----------------
__global__ void k_bnparam(int slot, const float* __restrict__ g,
                          const float* __restrict__ b, int M) {
    int m = threadIdx.x;
    if (m >= M) return;
    const float cnt = (float)NCOL;
    float mu  = g_sum[slot*128 + m] / cnt;
    float var = g_sq [slot*128 + m] / cnt - mu*mu;
    float a = g[m] * rsqrtf(var + BN_EPS);
    g_bna[slot*128 + m] = a;
    g_bnc[slot*128 + m] = b[m] - mu*a;
}

// ---------------- finalize: BN3 + ReLU + max over K ----------------
__global__ void __launch_bounds__(256) k_final(float* __restrict__ out) {
    int t = blockIdx.x*256 + threadIdx.x;
    if (t >= BB*128*SS) return;
    int s  = t & (SS-1);
    int bc = t >> 12;
    int c = bc & 127, b = bc >> 7;
    float a  = g_bna[2*128 + c];
    float cc = g_bnc[2*128 + c];
    const float4* z = (const float4*)(g_scr + OFF_C + (size_t)c*NCOL + (((size_t)(b*SS + s)) << 5));
    float m = 0.f;   // ReLU floor: max_k relu(x) == max(max_k x, 0)
    #pragma unroll
    for (int i = 0; i < 8; ++i) {
        float4 v = z[i];
        m = fmaxf(m, fmaf(a, v.x, cc));
        m = fmaxf(m, fmaf(a, v.y, cc));
        m = fmaxf(m, fmaf(a, v.z, cc));
        m = fmaxf(m, fmaf(a, v.w, cc));
    }
    out[BB*3*SS + t] = m;
}

// ---------------- launch ----------------
extern "C" void kernel_launch(void* const* d_in, const int* in_sizes, int n_in,
                              void* d_out, int out_size) {
    (void)in_sizes; (void)n_in; (void)out_size;
    const float* xyz   = (const float*)d_in[0];
    const float* feats = (const float*)d_in[1];
    const int*   perm  = (const int*)d_in[2];     // JAX w/o x64: int64 cast -> int32
    const float* w0 = (const float*)d_in[3];
    const float* g0 = (const float*)d_in[4];
    const float* b0 = (const float*)d_in[5];
    const float* w1 = (const float*)d_in[6];
    const float* g1 = (const float*)d_in[7];
    const float* b1 = (const float*)d_in[8];
    const float* w2 = (const float*)d_in[9];
    const float* g2 = (const float*)d_in[10];
    const float* b2 = (const float*)d_in[11];
    float* out = (float*)d_out;

    const int sm1 = (67*128 + 67*64)  * 4;   // 51456
    const int sm2 = (64*128 + 64*64)  * 4;   // 49152
    const int sm3 = (64*128 + 64*128) * 4;   // 65536
    cudaFuncSetAttribute(k_gemm<64,67,false>, cudaFuncAttributeMaxDynamicSharedMemorySize, sm1);
    cudaFuncSetAttribute(k_gemm<64,64,true >, cudaFuncAttributeMaxDynamicSharedMemorySize, sm2);
    cudaFuncSetAttribute(k_gemm<128,64,true>, cudaFuncAttributeMaxDynamicSharedMemorySize, sm3);

    k_newxyz<<<(BB*SS)/256, 256>>>(xyz, perm, out);
    k_xyzt  <<<(BB*NN)/256, 256>>>(xyz);
    k_featst<<<BB*2*(NN/32), 256>>>(feats);
    k_knn   <<<SS/8, 256>>>();
    k_buildx0<<<NCOL/128, 128>>>();

    k_gemm<64,67,false><<<NCOL/128, 128, sm1>>>(OFF_A, OFF_B, w0, 0, 0);
    k_bnparam<<<1,128>>>(0, g0, b0, 64);
    k_gemm<64,64,true ><<<NCOL/128, 128, sm2>>>(OFF_B, OFF_A, w1, 0, 1);
    k_bnparam<<<1,128>>>(1, g1, b1, 64);
    k_gemm<128,64,true><<<NCOL/128, 256, sm3>>>(OFF_A, OFF_C, w2, 1, 2);
    k_bnparam<<<1,128>>>(2, g2, b2, 128);
    k_final<<<(BB*128*SS)/256, 256>>>(out);
}

// round 5
// speedup vs baseline: 2.1851x; 1.5133x over previous
#include <cuda_runtime.h>
#include <cuda_bf16.h>
#include <math.h>
#include <stdint.h>

// ---------------- problem constants ----------------
#define BB 8
#define NN 16384
#define SS 4096
#define KK 32
#define CC 64
#define NCOL (BB*SS*KK)          // 1048576 columns (b,s,k)
#define NGRP (NCOL/32)           // 32768 (b,s) groups
#define BN_EPS 1e-5f
#define INF_F 3.0e38f

// ---------------- scratch layout (floats) ----------------
#define OFF_FEATS_T ((size_t)0)           // (B,N,64)
#define OFF_XYZT    ((size_t)8388608)     // (B,N,4)
#define OFF_NXYZT   ((size_t)8912896)     // (B,S,4)
#define OFF_Z1      ((size_t)9043968)     // 64 x NCOL
#define OFF_Z2      ((size_t)76152832)    // 64 x NCOL
#define OFF_MM      ((size_t)143261696)   // 128 x NGRP float2 (max,min)
#define OFF_WD      ((size_t)151650304)   // 3 x 16384 duplicated-pair weights
#define SCR_TOTAL   ((size_t)151699456)   // ~607 MB

__device__ float g_scr[SCR_TOTAL];
__device__ int   g_idx[SS*KK];
__device__ float g_ps[3][32][128];        // bucketed partial sums
__device__ float g_pq[3][32][128];        // bucketed partial sumsq
__device__ float g_bna[3*128];
__device__ float g_bnc[3*128];

static __device__ __forceinline__ int clampN(int n) {
    return n < 0 ? 0 : (n >= NN ? NN-1 : n);
}

// packed f32x2 FMA: acc = w*x + acc on both 32-bit lanes (sm_100 family feature)
#define FX2(acc, w, x) \
    asm("fma.rn.f32x2 %0, %1, %2, %0;" : "+l"(acc) : "l"(w), "l"(x))
#define UNPK(lo, hi, p) \
    asm("mov.b64 {%0, %1}, %2;" : "=f"(lo), "=f"(hi) : "l"(p))

// ---------------- prep: new_xyz output + query coords + clear stats ----------------
__global__ void __launch_bounds__(256) k_newxyz(const float* __restrict__ xyz,
                                                const int* __restrict__ perm,
                                                float* __restrict__ out) {
    int t = blockIdx.x*256 + threadIdx.x;
    if (t < 3*32*128) { ((float*)g_ps)[t] = 0.f; ((float*)g_pq)[t] = 0.f; }
    if (t >= BB*SS) return;
    int b = t / SS, s = t % SS;
    int n = clampN(perm[s]);
    #pragma unroll
    for (int c = 0; c < 3; ++c) {
        float v = xyz[((size_t)b*3 + c)*NN + n];
        out[((size_t)b*3 + c)*SS + s] = v;
        g_scr[OFF_NXYZT + ((size_t)(b*SS + s))*4 + c] = v;
    }
    g_scr[OFF_NXYZT + ((size_t)(b*SS + s))*4 + 3] = 0.f;
}

// ---------------- prep: xyz transpose (B,3,N) -> (B,N,4) ----------------
__global__ void __launch_bounds__(256) k_xyzt(const float* __restrict__ xyz) {
    int t = blockIdx.x*256 + threadIdx.x;
    if (t >= BB*NN) return;
    int b = t >> 14, n = t & (NN-1);
    #pragma unroll
    for (int c = 0; c < 3; ++c)
        g_scr[OFF_XYZT + ((size_t)(b*NN + n))*4 + c] = xyz[((size_t)b*3 + c)*NN + n];
    g_scr[OFF_XYZT + ((size_t)(b*NN + n))*4 + 3] = 0.f;
}

// ---------------- prep: feats transpose (B,64,N) -> (B,N,64) ----------------
__global__ void __launch_bounds__(256) k_featst(const float* __restrict__ feats) {
    __shared__ float tile[32][33];
    int blk = blockIdx.x;
    int nb  = blk & 511;
    int tmp = blk >> 9;
    int cb  = tmp & 1;
    int b   = tmp >> 1;
    int tx = threadIdx.x & 31, ty = threadIdx.x >> 5;
    int n0 = nb*32, c0 = cb*32;
    #pragma unroll
    for (int i = 0; i < 32; i += 8)
        tile[ty+i][tx] = feats[((size_t)b*CC + c0 + ty + i)*NN + n0 + tx];
    __syncthreads();
    #pragma unroll
    for (int i = 0; i < 32; i += 8)
        g_scr[OFF_FEATS_T + ((size_t)b*NN + n0 + ty + i)*CC + c0 + tx] = tile[tx][ty+i];
}

// ---------------- prep: duplicated-pair weight images [kk][2m] ----------------
__global__ void __launch_bounds__(256) k_prepw(const float* __restrict__ w0,
                                               const float* __restrict__ w1,
                                               const float* __restrict__ w2) {
    int t = blockIdx.x*256 + threadIdx.x;
    if (t >= 16384) return;
    int l, r;
    if      (t < 4096)  { l = 0; r = t; }
    else if (t < 8192)  { l = 1; r = t - 4096; }
    else                { l = 2; r = t - 8192; }
    int m = r >> 6, kk = r & 63;
    const float* W = (l == 0) ? w0 : (l == 1) ? w1 : w2;
    int stride = (l == 0) ? 67 : 64;
    int M2 = (l == 2) ? 256 : 128;
    float v = W[m*stride + kk];
    float* dst = g_scr + OFF_WD + (size_t)l*16384 + (size_t)kk*M2 + 2*m;
    dst[0] = v; dst[1] = v;
}

// ---------------- KNN: one warp per query, distributed register top-32 ----------------
__global__ void __launch_bounds__(256) k_knn() {
    __shared__ float4 s_tile[2048];
    int tid = threadIdx.x;
    int w = tid >> 5, lane = tid & 31;
    int q = blockIdx.x*8 + w;
    const float4* xt = (const float4*)(g_scr + OFF_XYZT);
    float4 qp = ((const float4*)(g_scr + OFF_NXYZT))[q];
    float qq = qp.x*qp.x + qp.y*qp.y + qp.z*qp.z;

    float myd = INF_F;
    int   myi = 0;
    float worst = INF_F;

    for (int tile = 0; tile < 8; ++tile) {
        __syncthreads();
        for (int i = tid; i < 2048; i += 256) {
            float4 p = xt[tile*2048 + i];
            p.w = p.x*p.x + p.y*p.y + p.z*p.z;
            s_tile[i] = p;
        }
        __syncthreads();
        #pragma unroll 4
        for (int j = 0; j < 64; ++j) {
            int ii = j*32 + lane;
            float4 p = s_tile[ii];
            float d = qq - 2.f*(qp.x*p.x + qp.y*p.y + qp.z*p.z) + p.w;
            int idx = tile*2048 + ii;
            unsigned hits = __ballot_sync(0xffffffffu, d < worst);
            while (hits) {
                int src = __ffs(hits) - 1;
                hits &= hits - 1;
                float dc = __shfl_sync(0xffffffffu, d, src);
                int   ic = __shfl_sync(0xffffffffu, idx, src);
                if (dc < worst) {
                    float v = myd; int pos = lane;
                    #pragma unroll
                    for (int off = 16; off; off >>= 1) {
                        float ov = __shfl_xor_sync(0xffffffffu, v, off);
                        int   op = __shfl_xor_sync(0xffffffffu, pos, off);
                        if (ov > v || (ov == v && op < pos)) { v = ov; pos = op; }
                    }
                    if (lane == pos) { myd = dc; myi = ic; }
                    float m = myd;
                    #pragma unroll
                    for (int off = 16; off; off >>= 1)
                        m = fmaxf(m, __shfl_xor_sync(0xffffffffu, m, off));
                    worst = m;
                }
            }
        }
    }
    g_idx[q*32 + lane] = myi;
}

// ---------------- FFMA2 GEMM, fused BN/ReLU in, stats + (layer2) maxpool out ----
// Block: 128 columns x M rows, K=64. Thread tile 8 rows x 8 cols (4 f32x2 pairs).
// smem floats: rel[512] | shx[64*132] | shw[64*2M]
#define XS 132

template<int LAYER>
__global__ void __launch_bounds__(LAYER==2 ? 256 : 128)
k_mma(const float* __restrict__ w0raw) {
    const int M = (LAYER == 2) ? 128 : 64;
    const int THREADS = M*2;
    extern __shared__ float smem[];
    float* rel = smem;                 // 512 (layer0 only)
    float* shx = smem + 512;           // 64*132
    float* shw = smem + 512 + 64*XS;   // 64*2M (duplicated pairs)
    int tid = threadIdx.x;
    int tx = tid & 15, ty = tid >> 4;
    size_t cb = (size_t)blockIdx.x * 128;

    // weights: copy duplicated-pair image
    {
        const float4* src = (const float4*)(g_scr + OFF_WD + (size_t)LAYER*16384);
        float4* dst = (float4*)shw;
        const int NF4 = 64*2*M/4;
        #pragma unroll
        for (int i = tid; i < NF4; i += THREADS) dst[i] = src[i];
    }

    // input tile -> shx[kk][col]
    if (LAYER == 0) {
        // gather: one thread per column
        int col = blockIdx.x*128 + tid;
        int G = col >> 5, k = col & 31;
        int s = G & (SS-1), b = G >> 12;
        int nidx = clampN(g_idx[s*32 + k]);
        const float4* fr = (const float4*)(g_scr + OFF_FEATS_T + ((size_t)b*NN + nidx)*CC);
        #pragma unroll
        for (int i = 0; i < 16; ++i) {
            float4 v = fr[i];
            shx[(i*4+0)*XS + tid] = v.x;
            shx[(i*4+1)*XS + tid] = v.y;
            shx[(i*4+2)*XS + tid] = v.z;
            shx[(i*4+3)*XS + tid] = v.w;
        }
        float4 p = ((const float4*)(g_scr + OFF_XYZT))[(size_t)b*NN + nidx];
        float4 q = ((const float4*)(g_scr + OFF_NXYZT))[(size_t)b*SS + s];
        ((float4*)rel)[tid] = make_float4(p.x - q.x, p.y - q.y, p.z - q.z, 0.f);
    } else {
        const int slot = LAYER - 1;
        const float* zin = g_scr + (LAYER == 1 ? OFF_Z1 : OFF_Z2);
        #pragma unroll
        for (int i = tid; i < 2048; i += THREADS) {
            int kk = i >> 5, c4 = i & 31;
            float4 v = *(const float4*)(zin + (size_t)kk*NCOL + cb + c4*4);
            float a = g_bna[slot*128 + kk], c = g_bnc[slot*128 + kk];
            v.x = fmaxf(fmaf(a, v.x, c), 0.f);
            v.y = fmaxf(fmaf(a, v.y, c), 0.f);
            v.z = fmaxf(fmaf(a, v.z, c), 0.f);
            v.w = fmaxf(fmaf(a, v.w, c), 0.f);
            *(float4*)(shx + kk*XS + c4*4) = v;
        }
    }
    __syncthreads();

    // ---- main loop: 32 FFMA2 per k ----
    unsigned long long acc[8][4];
    #pragma unroll
    for (int r = 0; r < 8; ++r)
        #pragma unroll
        for (int p = 0; p < 4; ++p) acc[r][p] = 0ull;

    #pragma unroll 4
    for (int kk = 0; kk < 64; ++kk) {
        const unsigned long long* xr = (const unsigned long long*)(shx + kk*XS + tx*8);
        unsigned long long x0 = xr[0], x1 = xr[1], x2 = xr[2], x3 = xr[3];
        const unsigned long long* wr = (const unsigned long long*)(shw + kk*2*M + ty*16);
        #pragma unroll
        for (int r = 0; r < 8; ++r) {
            unsigned long long wv = wr[r];
            FX2(acc[r][0], wv, x0);
            FX2(acc[r][1], wv, x1);
            FX2(acc[r][2], wv, x2);
            FX2(acc[r][3], wv, x3);
        }
    }

    // ---- epilogue ----
    float* zo = g_scr + (LAYER == 0 ? OFF_Z1 : OFF_Z2);
    float2* mm = (float2*)(g_scr + OFF_MM);
    int bkt = blockIdx.x & 31;
    float wx0 = 0.f, wx1 = 0.f, wx2 = 0.f;

    #pragma unroll
    for (int r = 0; r < 8; ++r) {
        int m = ty*8 + r;
        float v[8];
        #pragma unroll
        for (int p = 0; p < 4; ++p) UNPK(v[2*p], v[2*p+1], acc[r][p]);
        if (LAYER == 0) {
            wx0 = w0raw[m*67 + 64]; wx1 = w0raw[m*67 + 65]; wx2 = w0raw[m*67 + 66];
            #pragma unroll
            for (int j = 0; j < 8; ++j) {
                float4 rr = ((const float4*)rel)[tx*8 + j];
                v[j] = fmaf(wx0, rr.x, fmaf(wx1, rr.y, fmaf(wx2, rr.z, v[j])));
            }
        }
        float s_ = 0.f, q_ = 0.f;
        #pragma unroll
        for (int j = 0; j < 8; ++j) { s_ += v[j]; q_ = fmaf(v[j], v[j], q_); }
        #pragma unroll
        for (int o = 8; o; o >>= 1) {
            s_ += __shfl_down_sync(0xffffffffu, s_, o, 16);
            q_ += __shfl_down_sync(0xffffffffu, q_, o, 16);
        }
        if (tx == 0) {
            atomicAdd(&g_ps[LAYER][bkt][m], s_);
            atomicAdd(&g_pq[LAYER][bkt][m], q_);
        }
        if (LAYER < 2) {
            float* zr = zo + (size_t)m*NCOL + cb + tx*8;
            *(float4*)(zr)     = make_float4(v[0], v[1], v[2], v[3]);
            *(float4*)(zr + 4) = make_float4(v[4], v[5], v[6], v[7]);
        } else {
            float mx = v[0], mn = v[0];
            #pragma unroll
            for (int j = 1; j < 8; ++j) { mx = fmaxf(mx, v[j]); mn = fminf(mn, v[j]); }
            #pragma unroll
            for (int o = 2; o; o >>= 1) {
                mx = fmaxf(mx, __shfl_down_sync(0xffffffffu, mx, o, 4));
                mn = fminf(mn, __shfl_down_sync(0xffffffffu, mn, o, 4));
            }
            if ((tx & 3) == 0)
                mm[(size_t)m*NGRP + blockIdx.x*4 + (tx >> 2)] = make_float2(mx, mn);
        }
    }
}

// ---------------- BN affine params from bucketed stats ----------------
__global__ void k_bnparam(int slot, const float* __restrict__ g,
                          const float* __restrict__ b, int M) {
    int m = threadIdx.x;
    if (m >= M) return;
    float s = 0.f, q = 0.f;
    #pragma unroll
    for (int j = 0; j < 32; ++j) { s += g_ps[slot][j][m]; q += g_pq[slot][j][m]; }
    const float cnt = (float)NCOL;
    float mu  = s / cnt;
    float var = q / cnt - mu*mu;
    float a = g[m] * rsqrtf(var + BN_EPS);
    g_bna[slot*128 + m] = a;
    g_bnc[slot*128 + m] = b[m] - mu*a;
}

// ---------------- finalize: BN3 + ReLU + (pre-reduced) max over K ----------------
__global__ void __launch_bounds__(256) k_final(float* __restrict__ out) {
    int t = blockIdx.x*256 + threadIdx.x;
    if (t >= BB*128*SS) return;
    int s  = t & (SS-1);
    int bc = t >> 12;
    int c = bc & 127, b = bc >> 7;
    float a  = g_bna[2*128 + c];
    float cc = g_bnc[2*128 + c];
    const float2* mm = (const float2*)(g_scr + OFF_MM);
    float2 e = mm[(size_t)c*NGRP + b*SS + s];
    float z = (a >= 0.f) ? e.x : e.y;
    out[BB*3*SS + t] = fmaxf(fmaf(a, z, cc), 0.f);
}

// ---------------- launch ----------------
extern "C" void kernel_launch(void* const* d_in, const int* in_sizes, int n_in,
                              void* d_out, int out_size) {
    (void)in_sizes; (void)n_in; (void)out_size;
    const float* xyz   = (const float*)d_in[0];
    const float* feats = (const float*)d_in[1];
    const int*   perm  = (const int*)d_in[2];
    const float* w0 = (const float*)d_in[3];
    const float* g0 = (const float*)d_in[4];
    const float* b0 = (const float*)d_in[5];
    const float* w1 = (const float*)d_in[6];
    const float* g1 = (const float*)d_in[7];
    const float* b1 = (const float*)d_in[8];
    const float* w2 = (const float*)d_in[9];
    const float* g2 = (const float*)d_in[10];
    const float* b2 = (const float*)d_in[11];
    float* out = (float*)d_out;

    const int sm01 = (512 + 64*XS + 64*128) * 4;   // 68608
    const int sm2  = (512 + 64*XS + 64*256) * 4;   // 101376
    cudaFuncSetAttribute(k_mma<0>, cudaFuncAttributeMaxDynamicSharedMemorySize, sm01);
    cudaFuncSetAttribute(k_mma<1>, cudaFuncAttributeMaxDynamicSharedMemorySize, sm01);
    cudaFuncSetAttribute(k_mma<2>, cudaFuncAttributeMaxDynamicSharedMemorySize, sm2);

    k_newxyz<<<(BB*SS)/256, 256>>>(xyz, perm, out);
    k_xyzt  <<<(BB*NN)/256, 256>>>(xyz);
    k_featst<<<BB*2*(NN/32), 256>>>(feats);
    k_prepw <<<64, 256>>>(w0, w1, w2);
    k_knn   <<<SS/8, 256>>>();

    k_mma<0><<<NCOL/128, 128, sm01>>>(w0);
    k_bnparam<<<1,128>>>(0, g0, b0, 64);
    k_mma<1><<<NCOL/128, 128, sm01>>>(nullptr);
    k_bnparam<<<1,128>>>(1, g1, b1, 64);
    k_mma<2><<<NCOL/128, 256, sm2>>>(nullptr);
    k_bnparam<<<1,128>>>(2, g2, b2, 128);
    k_final<<<(BB*128*SS)/256, 256>>>(out);
}